// round 12
// baseline (speedup 1.0000x reference)
#include <cuda_runtime.h>

// HBV hydrological model scan, sm_103a — ILP-2 version.
// Each thread advances TWO independent (basin, nmul) cells through the
// 365-step recurrence, interleaving the two dependency chains to hide
// fixed-op and MUFU latency (kernel is latency-bound at occ ~26%).
//
// Cell mapping: thread tid handles cell tid (basin tid>>2) and
// cell tid+40000 (basin tid>>2 + 10000). Same m = tid&3 for both, so
// quad shuffles work identically for both chains.
//
// Outputs: d_out[0..T*B) = Qsim_avg, d_out[T*B..) = Qsim (T,B,4).

#define T_STEPS 365
#define BATCH   20000
#define NMUL    4
#define NCELLS  (BATCH * NMUL)
#define HALF_CELLS (NCELLS / 2)     // 40000
#define HALF_BATCH (BATCH / 2)      // 10000

__global__ __launch_bounds__(64)
void hbv_scan_ilp2_kernel(const float* __restrict__ forcing,
                          const float* __restrict__ pBETA,
                          const float* __restrict__ pFC,
                          const float* __restrict__ pK0,
                          const float* __restrict__ pK1,
                          const float* __restrict__ pK2,
                          const float* __restrict__ pLP,
                          const float* __restrict__ pPERC,
                          const float* __restrict__ pUZL,
                          const float* __restrict__ pTT,
                          const float* __restrict__ pCFMAX,
                          const float* __restrict__ pCFR,
                          const float* __restrict__ pCWH,
                          const float* __restrict__ pBETAET,
                          const float* __restrict__ pC,
                          float* __restrict__ qavg,   // (T, B)
                          float* __restrict__ qsim)   // (T, B, NMUL)
{
    const int tid = blockIdx.x * blockDim.x + threadIdx.x;
    if (tid >= HALF_CELLS) return;     // whole warps drop out (40000 % 32 == 0)

    const int cA = tid;                // cell A
    const int cB = tid + HALF_CELLS;   // cell B
    const int bA = tid >> 2;
    const int bB = bA + HALF_BATCH;
    const int m  = tid & 3;
    const float eps = 1e-6f;

    // ---- per-cell parameters, chain A ----
    const float BETA_A   = pBETA[cA];
    const float FC_A     = pFC[cA];
    const float K0_A     = pK0[cA];
    const float K1_A     = pK1[cA];
    const float K2_A     = pK2[cA];
    const float PERC_A   = pPERC[cA];
    const float UZL_A    = pUZL[cA];
    const float TT_A     = pTT[cA];
    const float CFMAX_A  = pCFMAX[cA];
    const float CWH_A    = pCWH[cA];
    const float BETAET_A = pBETAET[cA];
    const float C_A      = pC[cA];
    const float invFC_A   = 1.0f / FC_A;
    const float invLPFC_A = 1.0f / (pLP[cA] * FC_A);
    const float cfrcf_A   = pCFR[cA] * CFMAX_A;

    // ---- per-cell parameters, chain B ----
    const float BETA_B   = pBETA[cB];
    const float FC_B     = pFC[cB];
    const float K0_B     = pK0[cB];
    const float K1_B     = pK1[cB];
    const float K2_B     = pK2[cB];
    const float PERC_B   = pPERC[cB];
    const float UZL_B    = pUZL[cB];
    const float TT_B     = pTT[cB];
    const float CFMAX_B  = pCFMAX[cB];
    const float CWH_B    = pCWH[cB];
    const float BETAET_B = pBETAET[cB];
    const float C_B      = pC[cB];
    const float invFC_B   = 1.0f / FC_B;
    const float invLPFC_B = 1.0f / (pLP[cB] * FC_B);
    const float cfrcf_B   = pCFR[cB] * CFMAX_B;

    // ---- state ----
    float snowA = eps, meltA = 0.0f, smA = 0.0f, suzA = 0.0f, slzA = 0.0f;
    float snowB = eps, meltB = 0.0f, smB = 0.0f, suzB = 0.0f, slzB = 0.0f;

    const float* __restrict__ fA = forcing + (size_t)bA * 3;
    const float* __restrict__ fB = forcing + (size_t)bB * 3;

    // software-pipelined forcing: registers hold step t's values
    float pA = fA[0], tvA = fA[1], petA = fA[2];
    float pB = fB[0], tvB = fB[1], petB = fB[2];

    for (int t = 0; t < T_STEPS; ++t) {
        // prefetch step t+1 forcing (off the dependency chain)
        float npA = 0.f, ntvA = 0.f, npetA = 0.f;
        float npB = 0.f, ntvB = 0.f, npetB = 0.f;
        if (t + 1 < T_STEPS) {
            const float* gA = fA + (size_t)(t + 1) * (BATCH * 3);
            const float* gB = fB + (size_t)(t + 1) * (BATCH * 3);
            npA = gA[0]; ntvA = gA[1]; npetA = gA[2];
            npB = gB[0]; ntvB = gB[1]; npetB = gB[2];
        }

        // ================= chain A + chain B, interleaved by compiler =====
        // --- snow ---
        const float tdA = tvA - TT_A;
        const float tdB = tvB - TT_B;
        const float rainA = tdA > 0.0f ? pA : 0.0f;
        const float rainB = tdB > 0.0f ? pB : 0.0f;
        const float snowinA = tdA > 0.0f ? 0.0f : pA;
        const float snowinB = tdB > 0.0f ? 0.0f : pB;

        float snow1A = snowA + snowinA;
        float snow1B = snowB + snowinB;
        const float meltamtA = fminf(CFMAX_A * fmaxf(tdA, 0.0f), snow1A);
        const float meltamtB = fminf(CFMAX_B * fmaxf(tdB, 0.0f), snow1B);
        snow1A -= meltamtA;
        snow1B -= meltamtB;
        float melt1A = meltA + meltamtA;
        float melt1B = meltB + meltamtB;

        const float refrA = fminf(cfrcf_A * fmaxf(-tdA, 0.0f), melt1A);
        const float refrB = fminf(cfrcf_B * fmaxf(-tdB, 0.0f), melt1B);
        snowA = snow1A + refrA;
        snowB = snow1B + refrB;
        melt1A -= refrA;
        melt1B -= refrB;

        const float tosoilA = fmaxf(melt1A - CWH_A * snowA, 0.0f);
        const float tosoilB = fmaxf(melt1B - CWH_B * snowB, 0.0f);
        meltA = melt1A - tosoilA;
        meltB = melt1B - tosoilB;

        // --- soil ---
        const float swA = fminf(__powf(fmaxf(smA * invFC_A, eps), BETA_A), 1.0f);
        const float swB = fminf(__powf(fmaxf(smB * invFC_B, eps), BETA_B), 1.0f);
        const float rechA = (rainA + tosoilA) * swA;
        const float rechB = (rainB + tosoilB) * swB;
        float sm1A = smA + rainA + tosoilA - rechA;
        float sm1B = smB + rainB + tosoilB - rechB;
        const float excA = fmaxf(sm1A - FC_A, 0.0f);
        const float excB = fmaxf(sm1B - FC_B, 0.0f);
        sm1A -= excA;
        sm1B -= excB;

        const float efA = fminf(fmaxf(sm1A * invLPFC_A, 0.0f), 1.0f);
        const float efB = fminf(fmaxf(sm1B * invLPFC_B, 0.0f), 1.0f);
        const float evfA = fminf(__powf(fmaxf(efA, eps), BETAET_A), 1.0f);
        const float evfB = fminf(__powf(fmaxf(efB, eps), BETAET_B), 1.0f);
        const float etA = fminf(petA * evfA, sm1A);
        const float etB = fminf(petB * evfB, sm1B);
        const float smaeA = fmaxf(sm1A - etA, eps);
        const float smaeB = fmaxf(sm1B - etB, eps);

        const float srA = fminf(smaeA * invFC_A, 1.0f);
        const float srB = fminf(smaeB * invFC_B, 1.0f);
        const float capA = fminf(slzA, C_A * slzA * (1.0f - srA));
        const float capB = fminf(slzB, C_B * slzB * (1.0f - srB));
        smA = fmaxf(smaeA + capA, eps);
        smB = fmaxf(smaeB + capB, eps);
        const float slzacA = fmaxf(slzA - capA, eps);
        const float slzacB = fmaxf(slzB - capB, eps);

        // --- response ---
        float suz1A = suzA + rechA + excA;
        float suz1B = suzB + rechB + excB;
        const float percA = fminf(suz1A, PERC_A);
        const float percB = fminf(suz1B, PERC_B);
        suz1A -= percA;
        suz1B -= percB;
        const float slz1A = slzacA + percA;
        const float slz1B = slzacB + percB;

        const float q0A = K0_A * fmaxf(suz1A - UZL_A, 0.0f);
        const float q0B = K0_B * fmaxf(suz1B - UZL_B, 0.0f);
        suz1A -= q0A;
        suz1B -= q0B;
        const float q1A = K1_A * suz1A;
        const float q1B = K1_B * suz1B;
        suzA = suz1A - q1A;
        suzB = suz1B - q1B;
        const float q2A = K2_A * slz1A;
        const float q2B = K2_B * slz1B;
        slzA = slz1A - q2A;
        slzB = slz1B - q2B;

        const float qA = q0A + q1A + q2A;
        const float qB = q0B + q1B + q2B;

        // quad means (lanes are quad-aligned; full mask safe: whole warps active)
        float sA = qA + __shfl_xor_sync(0xffffffffu, qA, 1);
        float sB = qB + __shfl_xor_sync(0xffffffffu, qB, 1);
        sA += __shfl_xor_sync(0xffffffffu, sA, 2);
        sB += __shfl_xor_sync(0xffffffffu, sB, 2);

        qsim[(size_t)t * NCELLS + cA] = qA;
        qsim[(size_t)t * NCELLS + cB] = qB;
        if (m == 0) {
            qavg[(size_t)t * BATCH + bA] = sA * 0.25f;
            qavg[(size_t)t * BATCH + bB] = sB * 0.25f;
        }

        // rotate pipelined forcing
        pA = npA; tvA = ntvA; petA = npetA;
        pB = npB; tvB = ntvB; petB = npetB;
    }
}

extern "C" void kernel_launch(void* const* d_in, const int* in_sizes, int n_in,
                              void* d_out, int out_size)
{
    const float* forcing = (const float*)d_in[0];
    const float* pBETA   = (const float*)d_in[1];
    const float* pFC     = (const float*)d_in[2];
    const float* pK0     = (const float*)d_in[3];
    const float* pK1     = (const float*)d_in[4];
    const float* pK2     = (const float*)d_in[5];
    const float* pLP     = (const float*)d_in[6];
    const float* pPERC   = (const float*)d_in[7];
    const float* pUZL    = (const float*)d_in[8];
    const float* pTT     = (const float*)d_in[9];
    const float* pCFMAX  = (const float*)d_in[10];
    const float* pCFR    = (const float*)d_in[11];
    const float* pCWH    = (const float*)d_in[12];
    const float* pBETAET = (const float*)d_in[13];
    const float* pC      = (const float*)d_in[14];

    float* qavg = (float*)d_out;                           // (T, B)
    float* qsim = (float*)d_out + (size_t)T_STEPS * BATCH; // (T, B, NMUL)

    const int threads = 64;
    const int blocks  = (HALF_CELLS + threads - 1) / threads;  // 625
    hbv_scan_ilp2_kernel<<<blocks, threads>>>(forcing,
        pBETA, pFC, pK0, pK1, pK2, pLP, pPERC, pUZL, pTT,
        pCFMAX, pCFR, pCWH, pBETAET, pC,
        qavg, qsim);
}